// round 1
// baseline (speedup 1.0000x reference)
#include <cuda_runtime.h>
#include <math.h>

#define L 1024
#define DD 192
#define BSZ 4
#define KK 4
#define NST 16

// ---------------- scratch (no allocs allowed) ----------------
__device__ float  g_xz[BSZ*2*DD*L];     // in_proj output: channels [0,192)=xx, [192,384)=z (raw)
__device__ float  g_xx[BSZ*DD*L];       // conv+silu output
__device__ float  g_xs[BSZ*KK*DD*L];    // cross-scan gather
__device__ float  g_xdbl[BSZ*KK*38*L];  // x_proj output: rows 0..5 dt_rank, 6..21 B, 22..37 C
__device__ float  g_delta[BSZ*KK*DD*L]; // softplus(dts + dt_b)
__device__ float  g_y[BSZ*KK*DD*L];     // scan output
__device__ float  g_merged[BSZ*DD*L];
__device__ float  g_yn[BSZ*DD*L];
__device__ double g_stats[2*BSZ];

__device__ __forceinline__ float siluf(float x){ return x / (1.0f + __expf(-x)); }

// ---------------- generic small SGEMM ----------------
// Y[g] (M x 1024) = W[g % wsel] (M x Kc) * X[g] (Kc x 1024)
__global__ void sgemm_kernel(const float* __restrict__ W, const float* __restrict__ X,
                             float* __restrict__ Y, int M, int Kc,
                             int wPerG, int wsel, int xPerG, int yPerG)
{
    __shared__ float As[8][32];
    __shared__ float Bs[8][128];
    int g = blockIdx.z;
    const float* Wg = W + (g % wsel) * wPerG;
    const float* Xg = X + g * xPerG;
    float*       Yg = Y + g * yPerG;
    int m0 = blockIdx.y * 32;
    int n0 = blockIdx.x * 128;
    int tid = threadIdx.x;
    int tx = tid & 31, ty = tid >> 5;   // ty in [0,8)

    float acc[4][4];
#pragma unroll
    for (int i = 0; i < 4; i++)
#pragma unroll
        for (int j = 0; j < 4; j++) acc[i][j] = 0.f;

    int ntiles = Kc >> 3;
    for (int kt = 0; kt < ntiles; kt++) {
        // load A tile (8 x 32): thread (ty,tx) -> As[ty][tx]
        int m = m0 + tx;
        As[ty][tx] = (m < M) ? Wg[m * Kc + kt * 8 + ty] : 0.f;
        // load B tile (8 x 128): warp ty loads row ty, float4 per lane
        const float4* src = (const float4*)(Xg + (kt * 8 + ty) * L + n0);
        ((float4*)&Bs[ty][0])[tx] = src[tx];
        __syncthreads();
#pragma unroll
        for (int q = 0; q < 8; q++) {
            float a0 = As[q][ty*4+0], a1 = As[q][ty*4+1], a2 = As[q][ty*4+2], a3 = As[q][ty*4+3];
            float4 b4 = ((const float4*)&Bs[q][0])[tx];
            acc[0][0] = fmaf(a0,b4.x,acc[0][0]); acc[0][1] = fmaf(a0,b4.y,acc[0][1]);
            acc[0][2] = fmaf(a0,b4.z,acc[0][2]); acc[0][3] = fmaf(a0,b4.w,acc[0][3]);
            acc[1][0] = fmaf(a1,b4.x,acc[1][0]); acc[1][1] = fmaf(a1,b4.y,acc[1][1]);
            acc[1][2] = fmaf(a1,b4.z,acc[1][2]); acc[1][3] = fmaf(a1,b4.w,acc[1][3]);
            acc[2][0] = fmaf(a2,b4.x,acc[2][0]); acc[2][1] = fmaf(a2,b4.y,acc[2][1]);
            acc[2][2] = fmaf(a2,b4.z,acc[2][2]); acc[2][3] = fmaf(a2,b4.w,acc[2][3]);
            acc[3][0] = fmaf(a3,b4.x,acc[3][0]); acc[3][1] = fmaf(a3,b4.y,acc[3][1]);
            acc[3][2] = fmaf(a3,b4.z,acc[3][2]); acc[3][3] = fmaf(a3,b4.w,acc[3][3]);
        }
        __syncthreads();
    }
#pragma unroll
    for (int i = 0; i < 4; i++) {
        int m = m0 + ty * 4 + i;
        if (m < M) {
            float4 v = make_float4(acc[i][0], acc[i][1], acc[i][2], acc[i][3]);
            ((float4*)(Yg + m * L + n0))[tx] = v;
        }
    }
}

// ---------------- depthwise 3x3 conv + bias + silu ----------------
__global__ void conv_silu_kernel(const float* __restrict__ cw, const float* __restrict__ cb)
{
    int t = blockIdx.x * blockDim.x + threadIdx.x;
    if (t >= BSZ * DD * L) return;
    int l = t & (L - 1);
    int d = (t >> 10) % DD;
    int b = (t >> 10) / DD;
    int i = l >> 5, j = l & 31;
    const float* src = g_xz + (b * 2 * DD + d) * L;
    float acc = cb[d];
#pragma unroll
    for (int u = 0; u < 3; u++) {
        int r = i + u - 1;
        if ((unsigned)r < 32u) {
#pragma unroll
            for (int v = 0; v < 3; v++) {
                int c = j + v - 1;
                if ((unsigned)c < 32u)
                    acc = fmaf(cw[d * 9 + u * 3 + v], src[r * 32 + c], acc);
            }
        }
    }
    g_xx[(b * DD + d) * L + l] = siluf(acc);
}

// ---------------- cross scan gather ----------------
__global__ void cross_scan_kernel()
{
    int t = blockIdx.x * blockDim.x + threadIdx.x;
    if (t >= BSZ * KK * DD * L) return;
    int l = t & (L - 1);
    int rest = t >> 10;
    int d = rest % DD;
    int bk = rest / DD;     // b*4+k
    int k = bk & 3;
    int b = bk >> 2;
    int i = l >> 5, j = l & 31;
    int sr, sc;
    if (k == 0)      { sr = ((i & 1) == 0) ? j : 31 - j; sc = i; }
    else if (k == 1) { sr = ((i & 1) == 0) ? 31 - j : j; sc = 31 - i; }
    else if (k == 2) { sr = i; sc = ((i & 1) == 0) ? j : 31 - j; }
    else             { sr = 31 - i; sc = ((i & 1) == 0) ? 31 - j : j; }
    g_xs[t] = g_xx[(b * DD + d) * L + sr * 32 + sc];
}

// ---------------- dts projection + bias + softplus ----------------
__global__ void delta_kernel(const float* __restrict__ dt_w, const float* __restrict__ dt_b)
{
    int t = blockIdx.x * blockDim.x + threadIdx.x;
    if (t >= BSZ * KK * DD * L) return;
    int l = t & (L - 1);
    int rest = t >> 10;
    int d = rest % DD;
    int bk = rest / DD;
    int k = bk & 3;
    const float* xd = g_xdbl + bk * 38 * L;
    float acc = dt_b[k * DD + d];
#pragma unroll
    for (int r = 0; r < 6; r++)
        acc = fmaf(xd[r * L + l], dt_w[(k * DD + d) * 6 + r], acc);
    // softplus
    float sp = (acc > 20.f) ? acc : log1pf(__expf(acc));
    g_delta[t] = sp;
}

// ---------------- selective scan ----------------
// block = 256 threads: 16 d-sequences x 16 states. grid = B*K*(192/16) = 192 blocks.
__global__ void scan_kernel(const float* __restrict__ A_logs, const float* __restrict__ Ds)
{
    __shared__ float sB[16][65], sC[16][65], sDel[16][65], sU[16][65], sY[16][65];
    int blk = blockIdx.x;
    int dchunk = blk % 12;
    int k = (blk / 12) & 3;
    int b = blk / 48;
    int d0 = dchunk * 16;
    int tid = threadIdx.x;
    int n  = tid & 15;
    int di = tid >> 4;
    int d  = d0 + di;
    int bk = b * 4 + k;

    float Areg = -__expf(A_logs[(k * DD + d) * NST + n]);
    float Dreg = Ds[k * DD + d];

    const float* delP = g_delta + (bk * DD + d0) * L;
    const float* uP   = g_xs    + (bk * DD + d0) * L;
    const float* BP   = g_xdbl  + (bk * 38 + 6)  * L;
    const float* CP   = g_xdbl  + (bk * 38 + 22) * L;
    float*       yP   = g_y     + (bk * DD + d0) * L;

    float h = 0.f;
    for (int t0 = 0; t0 < L; t0 += 64) {
        for (int idx = tid; idx < 16 * 64; idx += 256) {
            int row = idx >> 6, col = idx & 63;
            sB[row][col]   = BP[row * L + t0 + col];
            sC[row][col]   = CP[row * L + t0 + col];
            sDel[row][col] = delP[row * L + t0 + col];
            sU[row][col]   = uP[row * L + t0 + col];
        }
        __syncthreads();
#pragma unroll 4
        for (int ll = 0; ll < 64; ll++) {
            float del = sDel[di][ll];
            float u   = sU[di][ll];
            float dA  = __expf(del * Areg);
            h = fmaf(dA, h, del * u * sB[n][ll]);
            float p = h * sC[n][ll];
            p += __shfl_xor_sync(0xffffffffu, p, 1);
            p += __shfl_xor_sync(0xffffffffu, p, 2);
            p += __shfl_xor_sync(0xffffffffu, p, 4);
            p += __shfl_xor_sync(0xffffffffu, p, 8);
            if (n == 0) sY[di][ll] = fmaf(Dreg, u, p);
        }
        __syncthreads();
        for (int idx = tid; idx < 16 * 64; idx += 256) {
            int row = idx >> 6, col = idx & 63;
            yP[row * L + t0 + col] = sY[row][col];
        }
        __syncthreads();
    }
}

// ---------------- zero stats ----------------
__global__ void zero_stats_kernel()
{
    if (threadIdx.x < 2 * BSZ) g_stats[threadIdx.x] = 0.0;
}

// ---------------- cross merge + layernorm stats ----------------
__global__ void merge_kernel()
{
    int b = blockIdx.y;
    int t = blockIdx.x * 256 + threadIdx.x;   // over DD*L
    int l = t & (L - 1);
    int d = t >> 10;
    int i = l >> 5, j = l & 31;
    int l0 = (j << 5)        + (((j & 1) == 0) ? i : 31 - i);
    int l1 = ((31 - j) << 5) + ((j & 1) ? 31 - i : i);
    int l2 = (i << 5)        + (((i & 1) == 0) ? j : 31 - j);
    int l3 = ((31 - i) << 5) + ((i & 1) ? 31 - j : j);
    const float* yb = g_y + ((b * 4) * DD + d) * L;
    float m = yb[l0] + yb[DD * L + l1] + yb[2 * DD * L + l2] + yb[3 * DD * L + l3];
    g_merged[(b * DD + d) * L + l] = m;

    __shared__ float s1[256], s2[256];
    int tx = threadIdx.x;
    s1[tx] = m;
    s2[tx] = m * m;
    __syncthreads();
    for (int s = 128; s > 0; s >>= 1) {
        if (tx < s) { s1[tx] += s1[tx + s]; s2[tx] += s2[tx + s]; }
        __syncthreads();
    }
    if (tx == 0) {
        atomicAdd(&g_stats[2 * b],     (double)s1[0]);
        atomicAdd(&g_stats[2 * b + 1], (double)s2[0]);
    }
}

// ---------------- normalize * gamma + beta, * silu(z) ----------------
__global__ void normalize_kernel(const float* __restrict__ gamma, const float* __restrict__ beta)
{
    int t = blockIdx.x * blockDim.x + threadIdx.x;
    if (t >= BSZ * DD * L) return;
    int l = t & (L - 1);
    int d = (t >> 10) % DD;
    int b = (t >> 10) / DD;
    double Ninv = 1.0 / (double)(DD * L);
    double mu_d = g_stats[2 * b] * Ninv;
    double var_d = g_stats[2 * b + 1] * Ninv - mu_d * mu_d;
    float mu = (float)mu_d;
    float inv = rsqrtf((float)var_d + 1e-6f);
    float zraw = g_xz[(b * 2 * DD + DD + d) * L + l];
    float z = siluf(zraw);
    float m = g_merged[(b * DD + d) * L + l];
    g_yn[(b * DD + d) * L + l] = fmaf(fmaf(m - mu, inv * gamma[d], beta[d] - 0.f), z, 0.f) ;
}

// ---------------- host launch ----------------
extern "C" void kernel_launch(void* const* d_in, const int* in_sizes, int n_in,
                              void* d_out, int out_size)
{
    const float* x        = (const float*)d_in[0];
    const float* in_proj  = (const float*)d_in[1];
    const float* conv_w   = (const float*)d_in[2];
    const float* conv_b   = (const float*)d_in[3];
    const float* x_proj_w = (const float*)d_in[4];
    const float* dt_w     = (const float*)d_in[5];
    const float* dt_b     = (const float*)d_in[6];
    const float* A_logs   = (const float*)d_in[7];
    const float* Ds       = (const float*)d_in[8];
    const float* gamma    = (const float*)d_in[9];
    const float* beta     = (const float*)d_in[10];
    const float* out_proj = (const float*)d_in[11];
    float* out = (float*)d_out;

    void *p_xz, *p_xs, *p_xdbl, *p_yn;
    cudaGetSymbolAddress(&p_xz,   g_xz);
    cudaGetSymbolAddress(&p_xs,   g_xs);
    cudaGetSymbolAddress(&p_xdbl, g_xdbl);
    cudaGetSymbolAddress(&p_yn,   g_yn);

    zero_stats_kernel<<<1, 32>>>();

    // 1) in_proj: (384x96) x (96x1024) per batch
    sgemm_kernel<<<dim3(8, 12, 4), 256>>>(in_proj, x, (float*)p_xz,
                                          384, 96, 0, 1, 96 * L, 384 * L);
    // 2) depthwise conv + silu
    conv_silu_kernel<<<(BSZ * DD * L) / 256, 256>>>(conv_w, conv_b);
    // 3) cross scan
    cross_scan_kernel<<<(BSZ * KK * DD * L) / 256, 256>>>();
    // 4) x_proj: (38x192) x (192x1024) per (b,k)
    sgemm_kernel<<<dim3(8, 2, 16), 256>>>(x_proj_w, (const float*)p_xs, (float*)p_xdbl,
                                          38, 192, 38 * 192, 4, 192 * L, 38 * L);
    // 5) delta
    delta_kernel<<<(BSZ * KK * DD * L) / 256, 256>>>(dt_w, dt_b);
    // 6) selective scan
    scan_kernel<<<192, 256>>>(A_logs, Ds);
    // 7) merge + stats
    merge_kernel<<<dim3((DD * L) / 256, BSZ), 256>>>();
    // 8) normalize + gate
    normalize_kernel<<<(BSZ * DD * L) / 256, 256>>>(gamma, beta);
    // 9) out_proj: (96x192) x (192x1024) per batch -> d_out
    sgemm_kernel<<<dim3(8, 3, 4), 256>>>(out_proj, (const float*)p_yn, out,
                                         96, 192, 0, 1, 192 * L, 96 * L);
    (void)in_sizes; (void)n_in; (void)out_size;
}